// round 3
// baseline (speedup 1.0000x reference)
#include <cuda_runtime.h>
#include <math.h>

#define B_   2
#define N_   4096
#define IC_  256
#define PC_  128
#define OC_  128
#define SCALE_ 0.08838834764831845f   // 1/sqrt(128)

// ---------------- scratch (device globals) ----------------------------------
static __device__ float g_rp  [(size_t)B_ * N_ * PC_];   // point_features^T [B,N,128]
static __device__ float g_ri  [(size_t)B_ * N_ * PC_];   // fc2(img^T)       [B,N,128]
static __device__ float g_S   [(size_t)B_ * N_ * N_];    // P = exp(scale*S) [B,N,N]
static __device__ float g_csum[B_ * N_];
static __device__ float g_rsum[B_ * N_];
static __device__ float g_outp[(size_t)B_ * N_ * PC_];
static __device__ float g_outi[(size_t)B_ * N_ * PC_];

// ---------------- mma helpers ------------------------------------------------
__device__ __forceinline__ unsigned tf32_of(float x) {
    unsigned r; asm("cvt.rna.tf32.f32 %0, %1;" : "=r"(r) : "f"(x)); return r;
}
__device__ __forceinline__ void split2(float x, unsigned& h, unsigned& l) {
    h = tf32_of(x);
    l = tf32_of(x - __uint_as_float(h));
}
__device__ __forceinline__ void mma_tf32(float* c, unsigned a0, unsigned a1,
                                         unsigned a2, unsigned a3,
                                         unsigned b0, unsigned b1) {
    asm volatile(
        "mma.sync.aligned.m16n8k8.row.col.f32.tf32.tf32.f32 "
        "{%0,%1,%2,%3}, {%4,%5,%6,%7}, {%8,%9}, {%0,%1,%2,%3};"
        : "+f"(c[0]), "+f"(c[1]), "+f"(c[2]), "+f"(c[3])
        : "r"(a0), "r"(a1), "r"(a2), "r"(a3), "r"(b0), "r"(b1));
}

#define LDM 136

// ---------------- kernel 0: zero the sum accumulators ------------------------
__global__ void k_zero() {
    int i = blockIdx.x * blockDim.x + threadIdx.x;
    if (i < B_ * N_) { g_csum[i] = 0.f; g_rsum[i] = 0.f; }
}

// ---------------- kernel 1: transpose point_features [B,PC,N] -> rp [B,N,PC]
__global__ void k_transpose(const float* __restrict__ pf) {
    __shared__ float tile[32][33];
    const int b  = blockIdx.z;
    const int n0 = blockIdx.x * 32;
    const int d0 = blockIdx.y * 32;
    const float* src = pf   + (size_t)b * PC_ * N_;
    float*       dst = g_rp + (size_t)b * N_ * PC_;
    const int tx = threadIdx.x, ty = threadIdx.y;   // (32, 8)
#pragma unroll
    for (int j = 0; j < 32; j += 8)
        tile[ty + j][tx] = src[(size_t)(d0 + ty + j) * N_ + n0 + tx];
    __syncthreads();
#pragma unroll
    for (int j = 0; j < 32; j += 8)
        dst[(size_t)(n0 + ty + j) * PC_ + d0 + tx] = tile[tx][ty + j];
}

// ---------------- kernel 2: ri = img^T @ fc2_w^T + fc2_b  (split-tf32 mma) ---
// tile 128(n) x 128(d), K=256, block 256 thr, warp tile 64x32
__global__ __launch_bounds__(256, 2) void k_ri(const float* __restrict__ img,
                                               const float* __restrict__ w,
                                               const float* __restrict__ bias) {
    const int b  = blockIdx.z;
    const int n0 = blockIdx.y * 128;
    const float* X = img  + (size_t)b * IC_ * N_;
    float*       R = g_ri + (size_t)b * N_ * PC_;

    __shared__ unsigned As[16][LDM], Asl[16][LDM];
    __shared__ unsigned Bs[16][LDM], Bsl[16][LDM];

    const int tid  = threadIdx.x;
    const int lane = tid & 31, wid = tid >> 5;
    const int wm = wid & 1, wn = wid >> 1;
    const int g = lane >> 2, t = lane & 3;

    float acc[4][4][4];
#pragma unroll
    for (int mf = 0; mf < 4; mf++)
#pragma unroll
        for (int nf = 0; nf < 4; nf++)
#pragma unroll
            for (int q = 0; q < 4; q++) acc[mf][nf][q] = 0.f;

    for (int k0 = 0; k0 < IC_; k0 += 16) {
        // As[kk][nn] = X[(k0+kk)*N + n0+nn]  (direct coalesced)
#pragma unroll
        for (int r = 0; r < 2; r++) {
            int idx = tid + r * 256;
            int kk = idx >> 5, nn = (idx & 31) * 4;
            float4 v = *(const float4*)&X[(size_t)(k0 + kk) * N_ + n0 + nn];
            split2(v.x, As[kk][nn + 0], Asl[kk][nn + 0]);
            split2(v.y, As[kk][nn + 1], Asl[kk][nn + 1]);
            split2(v.z, As[kk][nn + 2], Asl[kk][nn + 2]);
            split2(v.w, As[kk][nn + 3], Asl[kk][nn + 3]);
        }
        // Bs[kk][dd] = w[dd*IC + k0+kk]  (transposed fill)
#pragma unroll
        for (int r = 0; r < 2; r++) {
            int idx = tid + r * 256;
            int dd = idx >> 2, c = (idx & 3) * 4;
            float4 v = *(const float4*)&w[(size_t)dd * IC_ + k0 + c];
            split2(v.x, Bs[c + 0][dd], Bsl[c + 0][dd]);
            split2(v.y, Bs[c + 1][dd], Bsl[c + 1][dd]);
            split2(v.z, Bs[c + 2][dd], Bsl[c + 2][dd]);
            split2(v.w, Bs[c + 3][dd], Bsl[c + 3][dd]);
        }
        __syncthreads();
#pragma unroll
        for (int kk = 0; kk < 16; kk += 8) {
            unsigned ah[4][4], al[4][4], bh[4][2], bl[4][2];
#pragma unroll
            for (int mf = 0; mf < 4; mf++) {
                int m = wm * 64 + mf * 16 + g;
                ah[mf][0] = As [kk + t][m];     al[mf][0] = Asl[kk + t][m];
                ah[mf][1] = As [kk + t][m + 8]; al[mf][1] = Asl[kk + t][m + 8];
                ah[mf][2] = As [kk + t + 4][m];     al[mf][2] = Asl[kk + t + 4][m];
                ah[mf][3] = As [kk + t + 4][m + 8]; al[mf][3] = Asl[kk + t + 4][m + 8];
            }
#pragma unroll
            for (int nf = 0; nf < 4; nf++) {
                int n = wn * 32 + nf * 8 + g;
                bh[nf][0] = Bs [kk + t][n];     bl[nf][0] = Bsl[kk + t][n];
                bh[nf][1] = Bs [kk + t + 4][n]; bl[nf][1] = Bsl[kk + t + 4][n];
            }
#pragma unroll
            for (int mf = 0; mf < 4; mf++)
#pragma unroll
                for (int nf = 0; nf < 4; nf++) {
                    mma_tf32(acc[mf][nf], ah[mf][0], ah[mf][1], ah[mf][2], ah[mf][3],
                             bh[nf][0], bh[nf][1]);
                    mma_tf32(acc[mf][nf], ah[mf][0], ah[mf][1], ah[mf][2], ah[mf][3],
                             bl[nf][0], bl[nf][1]);
                    mma_tf32(acc[mf][nf], al[mf][0], al[mf][1], al[mf][2], al[mf][3],
                             bh[nf][0], bh[nf][1]);
                }
        }
        __syncthreads();
    }
#pragma unroll
    for (int mf = 0; mf < 4; mf++) {
        int row = n0 + wm * 64 + mf * 16 + g;
#pragma unroll
        for (int nf = 0; nf < 4; nf++) {
            int col = wn * 32 + nf * 8 + 2 * t;
            float b0 = bias[col], b1 = bias[col + 1];
            *(float2*)&R[(size_t)row * PC_ + col] =
                make_float2(acc[mf][nf][0] + b0, acc[mf][nf][1] + b1);
            *(float2*)&R[(size_t)(row + 8) * PC_ + col] =
                make_float2(acc[mf][nf][2] + b0, acc[mf][nf][3] + b1);
        }
    }
}

// ---------------- kernel 3: P = exp(scale * rp @ ri^T), + row/col sums -------
__global__ __launch_bounds__(256, 2) void k_s() {
    const int b  = blockIdx.z;
    const int i0 = blockIdx.y * 128;
    const int j0 = blockIdx.x * 128;
    const float* A  = g_rp + (size_t)b * N_ * PC_;
    const float* Bm = g_ri + (size_t)b * N_ * PC_;
    float*       Pp = g_S  + (size_t)b * N_ * N_;

    __shared__ unsigned As[16][LDM], Asl[16][LDM];
    __shared__ unsigned Bs[16][LDM], Bsl[16][LDM];
    __shared__ float shr[128], shc[128];

    const int tid  = threadIdx.x;
    const int lane = tid & 31, wid = tid >> 5;
    const int wm = wid & 1, wn = wid >> 1;
    const int g = lane >> 2, t = lane & 3;

    float acc[4][4][4];
#pragma unroll
    for (int mf = 0; mf < 4; mf++)
#pragma unroll
        for (int nf = 0; nf < 4; nf++)
#pragma unroll
            for (int q = 0; q < 4; q++) acc[mf][nf][q] = 0.f;

    for (int k0 = 0; k0 < PC_; k0 += 16) {
#pragma unroll
        for (int r = 0; r < 2; r++) {               // transposed fills, split at fill
            int idx = tid + r * 256;
            int i = idx >> 2, c = (idx & 3) * 4;
            float4 v = *(const float4*)&A[(size_t)(i0 + i) * PC_ + k0 + c];
            split2(v.x, As[c + 0][i], Asl[c + 0][i]);
            split2(v.y, As[c + 1][i], Asl[c + 1][i]);
            split2(v.z, As[c + 2][i], Asl[c + 2][i]);
            split2(v.w, As[c + 3][i], Asl[c + 3][i]);
            float4 u = *(const float4*)&Bm[(size_t)(j0 + i) * PC_ + k0 + c];
            split2(u.x, Bs[c + 0][i], Bsl[c + 0][i]);
            split2(u.y, Bs[c + 1][i], Bsl[c + 1][i]);
            split2(u.z, Bs[c + 2][i], Bsl[c + 2][i]);
            split2(u.w, Bs[c + 3][i], Bsl[c + 3][i]);
        }
        __syncthreads();
#pragma unroll
        for (int kk = 0; kk < 16; kk += 8) {
            unsigned ah[4][4], al[4][4], bh[4][2], bl[4][2];
#pragma unroll
            for (int mf = 0; mf < 4; mf++) {
                int m = wm * 64 + mf * 16 + g;
                ah[mf][0] = As [kk + t][m];     al[mf][0] = Asl[kk + t][m];
                ah[mf][1] = As [kk + t][m + 8]; al[mf][1] = Asl[kk + t][m + 8];
                ah[mf][2] = As [kk + t + 4][m];     al[mf][2] = Asl[kk + t + 4][m];
                ah[mf][3] = As [kk + t + 4][m + 8]; al[mf][3] = Asl[kk + t + 4][m + 8];
            }
#pragma unroll
            for (int nf = 0; nf < 4; nf++) {
                int n = wn * 32 + nf * 8 + g;
                bh[nf][0] = Bs [kk + t][n];     bl[nf][0] = Bsl[kk + t][n];
                bh[nf][1] = Bs [kk + t + 4][n]; bl[nf][1] = Bsl[kk + t + 4][n];
            }
#pragma unroll
            for (int mf = 0; mf < 4; mf++)
#pragma unroll
                for (int nf = 0; nf < 4; nf++) {
                    mma_tf32(acc[mf][nf], ah[mf][0], ah[mf][1], ah[mf][2], ah[mf][3],
                             bh[nf][0], bh[nf][1]);
                    mma_tf32(acc[mf][nf], ah[mf][0], ah[mf][1], ah[mf][2], ah[mf][3],
                             bl[nf][0], bl[nf][1]);
                    mma_tf32(acc[mf][nf], al[mf][0], al[mf][1], al[mf][2], al[mf][3],
                             bh[nf][0], bh[nf][1]);
                }
        }
        __syncthreads();
    }

    if (tid < 128) { shr[tid] = 0.f; shc[tid] = 0.f; }
    __syncthreads();

    float rs[4][2] = {{0.f,0.f},{0.f,0.f},{0.f,0.f},{0.f,0.f}};
    float cs[4][2] = {{0.f,0.f},{0.f,0.f},{0.f,0.f},{0.f,0.f}};
#pragma unroll
    for (int mf = 0; mf < 4; mf++) {
        int row = i0 + wm * 64 + mf * 16 + g;
#pragma unroll
        for (int nf = 0; nf < 4; nf++) {
            int col = j0 + wn * 32 + nf * 8 + 2 * t;
            float p0 = __expf(acc[mf][nf][0] * SCALE_);
            float p1 = __expf(acc[mf][nf][1] * SCALE_);
            float p2 = __expf(acc[mf][nf][2] * SCALE_);
            float p3 = __expf(acc[mf][nf][3] * SCALE_);
            *(float2*)&Pp[(size_t)row * N_ + col]       = make_float2(p0, p1);
            *(float2*)&Pp[(size_t)(row + 8) * N_ + col] = make_float2(p2, p3);
            rs[mf][0] += p0 + p1; rs[mf][1] += p2 + p3;
            cs[nf][0] += p0 + p2; cs[nf][1] += p1 + p3;
        }
    }
#pragma unroll
    for (int mf = 0; mf < 4; mf++)
#pragma unroll
        for (int h = 0; h < 2; h++) {
            float v = rs[mf][h];
            v += __shfl_xor_sync(0xffffffffu, v, 1);
            v += __shfl_xor_sync(0xffffffffu, v, 2);
            if (t == 0) atomicAdd(&shr[wm * 64 + mf * 16 + h * 8 + g], v);
        }
#pragma unroll
    for (int nf = 0; nf < 4; nf++)
#pragma unroll
        for (int q = 0; q < 2; q++) {
            float v = cs[nf][q];
            v += __shfl_xor_sync(0xffffffffu, v, 4);
            v += __shfl_xor_sync(0xffffffffu, v, 8);
            v += __shfl_xor_sync(0xffffffffu, v, 16);
            if (g == 0) atomicAdd(&shc[wn * 32 + nf * 8 + 2 * t + q], v);
        }
    __syncthreads();
    if (tid < 128) {
        atomicAdd(&g_rsum[b * N_ + i0 + tid], shr[tid]);
        atomicAdd(&g_csum[b * N_ + j0 + tid], shc[tid]);
    }
}

// ---------------- kernel 4: AV GEMMs (tf32 single-pass, cvt at fill) ---------
__global__ __launch_bounds__(256, 2) void k_av() {
    const int mode = blockIdx.x;
    const int b    = blockIdx.z;
    const int i0   = blockIdx.y * 128;
    const float* Pp  = g_S + (size_t)b * N_ * N_;
    const float* V   = (mode == 0 ? g_rp : g_ri) + (size_t)b * N_ * PC_;
    const float* sum = (mode == 0 ? g_csum : g_rsum) + b * N_;
    float*       D   = (mode == 0 ? g_outp : g_outi) + (size_t)b * N_ * PC_;

    __shared__ unsigned As[16][LDM];
    __shared__ unsigned Bs[16][LDM];

    const int tid  = threadIdx.x;
    const int lane = tid & 31, wid = tid >> 5;
    const int wm = wid & 1, wn = wid >> 1;
    const int g = lane >> 2, t = lane & 3;

    float acc[4][4][4];
#pragma unroll
    for (int mf = 0; mf < 4; mf++)
#pragma unroll
        for (int nf = 0; nf < 4; nf++)
#pragma unroll
            for (int q = 0; q < 4; q++) acc[mf][nf][q] = 0.f;

    for (int k0 = 0; k0 < N_; k0 += 16) {
        if (mode == 0) {      // As[k][i] = P[(i0+i)*N + k0+k]
#pragma unroll
            for (int r = 0; r < 2; r++) {
                int idx = tid + r * 256;
                int i = idx >> 2, c = (idx & 3) * 4;
                float4 v = *(const float4*)&Pp[(size_t)(i0 + i) * N_ + k0 + c];
                As[c + 0][i] = tf32_of(v.x); As[c + 1][i] = tf32_of(v.y);
                As[c + 2][i] = tf32_of(v.z); As[c + 3][i] = tf32_of(v.w);
            }
        } else {              // As[k][i] = P[(k0+k)*N + i0+i]
#pragma unroll
            for (int r = 0; r < 2; r++) {
                int idx = tid + r * 256;
                int k = idx >> 5, ic = (idx & 31) * 4;
                float4 v = *(const float4*)&Pp[(size_t)(k0 + k) * N_ + i0 + ic];
                As[k][ic + 0] = tf32_of(v.x); As[k][ic + 1] = tf32_of(v.y);
                As[k][ic + 2] = tf32_of(v.z); As[k][ic + 3] = tf32_of(v.w);
            }
        }
        {                     // Bs[k][d] = V[(k0+k)*128 + d] / sum[k0+k]
#pragma unroll
            for (int r = 0; r < 2; r++) {
                int idx = tid + r * 256;
                int k = idx >> 5, dc = (idx & 31) * 4;
                float inv = __fdividef(1.0f, sum[k0 + k]);
                float4 v = *(const float4*)&V[(size_t)(k0 + k) * PC_ + dc];
                Bs[k][dc + 0] = tf32_of(v.x * inv); Bs[k][dc + 1] = tf32_of(v.y * inv);
                Bs[k][dc + 2] = tf32_of(v.z * inv); Bs[k][dc + 3] = tf32_of(v.w * inv);
            }
        }
        __syncthreads();
#pragma unroll
        for (int kk = 0; kk < 16; kk += 8) {
            unsigned a[4][4], bb[4][2];
#pragma unroll
            for (int mf = 0; mf < 4; mf++) {
                int m = wm * 64 + mf * 16 + g;
                a[mf][0] = As[kk + t][m];
                a[mf][1] = As[kk + t][m + 8];
                a[mf][2] = As[kk + t + 4][m];
                a[mf][3] = As[kk + t + 4][m + 8];
            }
#pragma unroll
            for (int nf = 0; nf < 4; nf++) {
                int n = wn * 32 + nf * 8 + g;
                bb[nf][0] = Bs[kk + t][n];
                bb[nf][1] = Bs[kk + t + 4][n];
            }
#pragma unroll
            for (int mf = 0; mf < 4; mf++)
#pragma unroll
                for (int nf = 0; nf < 4; nf++)
                    mma_tf32(acc[mf][nf], a[mf][0], a[mf][1], a[mf][2], a[mf][3],
                             bb[nf][0], bb[nf][1]);
        }
        __syncthreads();
    }
#pragma unroll
    for (int mf = 0; mf < 4; mf++) {
        int row = i0 + wm * 64 + mf * 16 + g;
#pragma unroll
        for (int nf = 0; nf < 4; nf++) {
            int col = wn * 32 + nf * 8 + 2 * t;
            *(float2*)&D[(size_t)row * PC_ + col]       = make_float2(acc[mf][nf][0], acc[mf][nf][1]);
            *(float2*)&D[(size_t)(row + 8) * PC_ + col] = make_float2(acc[mf][nf][2], acc[mf][nf][3]);
        }
    }
}

// ---------------- kernel 5: conv1d(k=1)+BN+ReLU via split-tf32 mma -----------
// C[o][n] = sum_c w[o][c] * fusion[n][c];  tile 128(o) x 128(n), K=256
__global__ __launch_bounds__(256, 2) void k_conv(const float* __restrict__ w,
                                                 const float* __restrict__ cb,
                                                 const float* __restrict__ gamma,
                                                 const float* __restrict__ beta,
                                                 const float* __restrict__ mean,
                                                 const float* __restrict__ var,
                                                 float* __restrict__ out) {
    const int b  = blockIdx.z;
    const int n0 = blockIdx.y * 128;
    const float* P = g_outp + (size_t)b * N_ * PC_;
    const float* I = g_outi + (size_t)b * N_ * PC_;

    __shared__ unsigned As[16][LDM], Asl[16][LDM];
    __shared__ unsigned Bs[16][LDM], Bsl[16][LDM];

    const int tid  = threadIdx.x;
    const int lane = tid & 31, wid = tid >> 5;
    const int wm = wid & 1, wn = wid >> 1;
    const int g = lane >> 2, t = lane & 3;

    float acc[4][4][4];
#pragma unroll
    for (int mf = 0; mf < 4; mf++)
#pragma unroll
        for (int nf = 0; nf < 4; nf++)
#pragma unroll
            for (int q = 0; q < 4; q++) acc[mf][nf][q] = 0.f;

    for (int k0 = 0; k0 < 2 * PC_; k0 += 16) {
        // As[kk][oo] = w[oo*256 + k0+kk]
#pragma unroll
        for (int r = 0; r < 2; r++) {
            int idx = tid + r * 256;
            int oo = idx >> 2, c = (idx & 3) * 4;
            float4 v = *(const float4*)&w[(size_t)oo * (2 * PC_) + k0 + c];
            split2(v.x, As[c + 0][oo], Asl[c + 0][oo]);
            split2(v.y, As[c + 1][oo], Asl[c + 1][oo]);
            split2(v.z, As[c + 2][oo], Asl[c + 2][oo]);
            split2(v.w, As[c + 3][oo], Asl[c + 3][oo]);
        }
        // Bs[kk][nn] = fusion[n0+nn][k0+kk]
#pragma unroll
        for (int r = 0; r < 2; r++) {
            int idx = tid + r * 256;
            int nn = idx >> 2, c = (idx & 3) * 4;
            const float* src = (k0 < PC_) ? &P[(size_t)(n0 + nn) * PC_ + k0 + c]
                                          : &I[(size_t)(n0 + nn) * PC_ + k0 - PC_ + c];
            float4 v = *(const float4*)src;
            split2(v.x, Bs[c + 0][nn], Bsl[c + 0][nn]);
            split2(v.y, Bs[c + 1][nn], Bsl[c + 1][nn]);
            split2(v.z, Bs[c + 2][nn], Bsl[c + 2][nn]);
            split2(v.w, Bs[c + 3][nn], Bsl[c + 3][nn]);
        }
        __syncthreads();
#pragma unroll
        for (int kk = 0; kk < 16; kk += 8) {
            unsigned ah[4][4], al[4][4], bh[4][2], bl[4][2];
#pragma unroll
            for (int mf = 0; mf < 4; mf++) {
                int m = wm * 64 + mf * 16 + g;
                ah[mf][0] = As [kk + t][m];     al[mf][0] = Asl[kk + t][m];
                ah[mf][1] = As [kk + t][m + 8]; al[mf][1] = Asl[kk + t][m + 8];
                ah[mf][2] = As [kk + t + 4][m];     al[mf][2] = Asl[kk + t + 4][m];
                ah[mf][3] = As [kk + t + 4][m + 8]; al[mf][3] = Asl[kk + t + 4][m + 8];
            }
#pragma unroll
            for (int nf = 0; nf < 4; nf++) {
                int n = wn * 32 + nf * 8 + g;
                bh[nf][0] = Bs [kk + t][n];     bl[nf][0] = Bsl[kk + t][n];
                bh[nf][1] = Bs [kk + t + 4][n]; bl[nf][1] = Bsl[kk + t + 4][n];
            }
#pragma unroll
            for (int mf = 0; mf < 4; mf++)
#pragma unroll
                for (int nf = 0; nf < 4; nf++) {
                    mma_tf32(acc[mf][nf], ah[mf][0], ah[mf][1], ah[mf][2], ah[mf][3],
                             bh[nf][0], bh[nf][1]);
                    mma_tf32(acc[mf][nf], ah[mf][0], ah[mf][1], ah[mf][2], ah[mf][3],
                             bl[nf][0], bl[nf][1]);
                    mma_tf32(acc[mf][nf], al[mf][0], al[mf][1], al[mf][2], al[mf][3],
                             bh[nf][0], bh[nf][1]);
                }
        }
        __syncthreads();
    }
#pragma unroll
    for (int mf = 0; mf < 4; mf++) {
        int o0 = wm * 64 + mf * 16 + g;
        int o1 = o0 + 8;
        float gm0 = gamma[o0] * rsqrtf(var[o0] + 1e-5f);
        float gm1 = gamma[o1] * rsqrtf(var[o1] + 1e-5f);
        float ba0 = gm0 * (cb[o0] - mean[o0]) + beta[o0];
        float ba1 = gm1 * (cb[o1] - mean[o1]) + beta[o1];
        float* out0 = out + (size_t)b * OC_ * N_ + (size_t)o0 * N_;
        float* out1 = out + (size_t)b * OC_ * N_ + (size_t)o1 * N_;
#pragma unroll
        for (int nf = 0; nf < 4; nf++) {
            int col = n0 + wn * 32 + nf * 8 + 2 * t;
            *(float2*)&out0[col] = make_float2(
                fmaxf(gm0 * acc[mf][nf][0] + ba0, 0.f),
                fmaxf(gm0 * acc[mf][nf][1] + ba0, 0.f));
            *(float2*)&out1[col] = make_float2(
                fmaxf(gm1 * acc[mf][nf][2] + ba1, 0.f),
                fmaxf(gm1 * acc[mf][nf][3] + ba1, 0.f));
        }
    }
}

// ---------------- launch -----------------------------------------------------
extern "C" void kernel_launch(void* const* d_in, const int* in_sizes, int n_in,
                              void* d_out, int out_size) {
    const float* pf     = (const float*)d_in[0];
    const float* img    = (const float*)d_in[1];
    const float* fc2_w  = (const float*)d_in[2];
    const float* fc2_b  = (const float*)d_in[3];
    const float* conv_w = (const float*)d_in[4];
    const float* conv_b = (const float*)d_in[5];
    const float* gamma  = (const float*)d_in[6];
    const float* beta   = (const float*)d_in[7];
    const float* mean   = (const float*)d_in[8];
    const float* var    = (const float*)d_in[9];
    float* out = (float*)d_out;

    k_zero     <<<(B_ * N_ + 511) / 512, 512>>>();
    k_transpose<<<dim3(N_ / 32, PC_ / 32, B_), dim3(32, 8)>>>(pf);
    k_ri       <<<dim3(1, N_ / 128, B_),        256>>>(img, fc2_w, fc2_b);
    k_s        <<<dim3(N_ / 128, N_ / 128, B_), 256>>>();
    k_av       <<<dim3(2, N_ / 128, B_),        256>>>();
    k_conv     <<<dim3(1, N_ / 128, B_),        256>>>(conv_w, conv_b, gamma, beta,
                                                       mean, var, out);
}

// round 4
// speedup vs baseline: 1.1303x; 1.1303x over previous
#include <cuda_runtime.h>
#include <math.h>

#define B_   2
#define N_   4096
#define IC_  256
#define PC_  128
#define OC_  128
#define SCALE_ 0.08838834764831845f   // 1/sqrt(128)

// ---------------- scratch (device globals) ----------------------------------
static __device__ float g_rp  [(size_t)B_ * N_ * PC_];
static __device__ float g_ri  [(size_t)B_ * N_ * PC_];
static __device__ float g_S   [(size_t)B_ * N_ * N_];    // P = exp(scale*S)
static __device__ float g_csum[B_ * N_];
static __device__ float g_rsum[B_ * N_];
static __device__ float g_outp[(size_t)B_ * N_ * PC_];
static __device__ float g_outi[(size_t)B_ * N_ * PC_];

// ---------------- mma helpers ------------------------------------------------
__device__ __forceinline__ unsigned tf32_of(float x) {
    unsigned r; asm("cvt.rna.tf32.f32 %0, %1;" : "=r"(r) : "f"(x)); return r;
}
__device__ __forceinline__ void mma_tf32(float* c, unsigned a0, unsigned a1,
                                         unsigned a2, unsigned a3,
                                         unsigned b0, unsigned b1) {
    asm volatile(
        "mma.sync.aligned.m16n8k8.row.col.f32.tf32.tf32.f32 "
        "{%0,%1,%2,%3}, {%4,%5,%6,%7}, {%8,%9}, {%0,%1,%2,%3};"
        : "+f"(c[0]), "+f"(c[1]), "+f"(c[2]), "+f"(c[3])
        : "r"(a0), "r"(a1), "r"(a2), "r"(a3), "r"(b0), "r"(b1));
}

#define LDM 136

// ---------------- kernel 0: zero the sum accumulators ------------------------
__global__ void k_zero() {
    int i = blockIdx.x * blockDim.x + threadIdx.x;
    if (i < B_ * N_) { g_csum[i] = 0.f; g_rsum[i] = 0.f; }
}

// ---------------- kernel 1: transpose point_features [B,PC,N] -> rp [B,N,PC]
__global__ void k_transpose(const float* __restrict__ pf) {
    __shared__ float tile[32][33];
    const int b  = blockIdx.z;
    const int n0 = blockIdx.x * 32;
    const int d0 = blockIdx.y * 32;
    const float* src = pf   + (size_t)b * PC_ * N_;
    float*       dst = g_rp + (size_t)b * N_ * PC_;
    const int tx = threadIdx.x, ty = threadIdx.y;   // (32, 8)
#pragma unroll
    for (int j = 0; j < 32; j += 8)
        tile[ty + j][tx] = src[(size_t)(d0 + ty + j) * N_ + n0 + tx];
    __syncthreads();
#pragma unroll
    for (int j = 0; j < 32; j += 8)
        dst[(size_t)(n0 + ty + j) * PC_ + d0 + tx] = tile[tx][ty + j];
}

// ---------------- kernel 2: ri = img^T @ fc2_w^T + fc2_b  (scalar fp32) ------
__global__ void k_ri(const float* __restrict__ img, const float* __restrict__ w,
                     const float* __restrict__ bias) {
    const int b  = blockIdx.z;
    const int n0 = blockIdx.y * 64;
    const float* X = img  + (size_t)b * IC_ * N_;
    float*       R = g_ri + (size_t)b * N_ * PC_;
    __shared__ float As[16][64];
    __shared__ float Bs[16][128];
    const int tx = threadIdx.x, ty = threadIdx.y;
    const int tid = ty * 16 + tx;
    float acc[4][8];
#pragma unroll
    for (int i = 0; i < 4; i++)
#pragma unroll
        for (int j = 0; j < 8; j++) acc[i][j] = 0.f;

    for (int k0 = 0; k0 < IC_; k0 += 16) {
        {
            int l = tid * 4, kk = l / 64, nn = l % 64;
            float4 v = *(const float4*)&X[(size_t)(k0 + kk) * N_ + n0 + nn];
            *(float4*)&As[kk][nn] = v;
        }
        {
            int l = tid * 8, dd = l / 16, kk = l % 16;
            float4 v0 = *(const float4*)&w[(size_t)dd * IC_ + k0 + kk];
            float4 v1 = *(const float4*)&w[(size_t)dd * IC_ + k0 + kk + 4];
            Bs[kk + 0][dd] = v0.x; Bs[kk + 1][dd] = v0.y;
            Bs[kk + 2][dd] = v0.z; Bs[kk + 3][dd] = v0.w;
            Bs[kk + 4][dd] = v1.x; Bs[kk + 5][dd] = v1.y;
            Bs[kk + 6][dd] = v1.z; Bs[kk + 7][dd] = v1.w;
        }
        __syncthreads();
#pragma unroll
        for (int kk = 0; kk < 16; kk++) {
            float a[4], bb[8];
#pragma unroll
            for (int i = 0; i < 4; i++) a[i] = As[kk][ty * 4 + i];
#pragma unroll
            for (int j = 0; j < 8; j++) bb[j] = Bs[kk][tx * 8 + j];
#pragma unroll
            for (int i = 0; i < 4; i++)
#pragma unroll
                for (int j = 0; j < 8; j++) acc[i][j] += a[i] * bb[j];
        }
        __syncthreads();
    }
#pragma unroll
    for (int i = 0; i < 4; i++) {
        int n = n0 + ty * 4 + i;
#pragma unroll
        for (int j = 0; j < 8; j++) {
            int d = tx * 8 + j;
            R[(size_t)n * PC_ + d] = acc[i][j] + bias[d];
        }
    }
}

// ---------------- kernel 3: P = exp(scale * rp @ ri^T) + row/col sums --------
// Single-pass tf32 mma, cvt at fill. Block 256, tile 128x128, warp 64x32.
__global__ __launch_bounds__(256, 2) void k_s() {
    const int b  = blockIdx.z;
    const int i0 = blockIdx.y * 128;
    const int j0 = blockIdx.x * 128;
    const float* A  = g_rp + (size_t)b * N_ * PC_;
    const float* Bm = g_ri + (size_t)b * N_ * PC_;
    float*       Pp = g_S  + (size_t)b * N_ * N_;

    __shared__ unsigned As[16][LDM];
    __shared__ unsigned Bs[16][LDM];
    __shared__ float shr[128], shc[128];

    const int tid  = threadIdx.x;
    const int lane = tid & 31, wid = tid >> 5;
    const int wm = wid & 1, wn = wid >> 1;
    const int g = lane >> 2, t = lane & 3;

    float acc[4][4][4];
#pragma unroll
    for (int mf = 0; mf < 4; mf++)
#pragma unroll
        for (int nf = 0; nf < 4; nf++)
#pragma unroll
            for (int q = 0; q < 4; q++) acc[mf][nf][q] = 0.f;

    for (int k0 = 0; k0 < PC_; k0 += 16) {
#pragma unroll
        for (int r = 0; r < 2; r++) {               // transposed fills, cvt at fill
            int idx = tid + r * 256;
            int i = idx >> 2, c = (idx & 3) * 4;
            float4 v = *(const float4*)&A[(size_t)(i0 + i) * PC_ + k0 + c];
            As[c + 0][i] = tf32_of(v.x); As[c + 1][i] = tf32_of(v.y);
            As[c + 2][i] = tf32_of(v.z); As[c + 3][i] = tf32_of(v.w);
            float4 u = *(const float4*)&Bm[(size_t)(j0 + i) * PC_ + k0 + c];
            Bs[c + 0][i] = tf32_of(u.x); Bs[c + 1][i] = tf32_of(u.y);
            Bs[c + 2][i] = tf32_of(u.z); Bs[c + 3][i] = tf32_of(u.w);
        }
        __syncthreads();
#pragma unroll
        for (int kk = 0; kk < 16; kk += 8) {
            unsigned a[4][4], bb[4][2];
#pragma unroll
            for (int mf = 0; mf < 4; mf++) {
                int m = wm * 64 + mf * 16 + g;
                a[mf][0] = As[kk + t][m];
                a[mf][1] = As[kk + t][m + 8];
                a[mf][2] = As[kk + t + 4][m];
                a[mf][3] = As[kk + t + 4][m + 8];
            }
#pragma unroll
            for (int nf = 0; nf < 4; nf++) {
                int n = wn * 32 + nf * 8 + g;
                bb[nf][0] = Bs[kk + t][n];
                bb[nf][1] = Bs[kk + t + 4][n];
            }
#pragma unroll
            for (int mf = 0; mf < 4; mf++)
#pragma unroll
                for (int nf = 0; nf < 4; nf++)
                    mma_tf32(acc[mf][nf], a[mf][0], a[mf][1], a[mf][2], a[mf][3],
                             bb[nf][0], bb[nf][1]);
        }
        __syncthreads();
    }

    // epilogue: P = exp(scale*acc), store, reduce row/col sums
    if (tid < 128) { shr[tid] = 0.f; shc[tid] = 0.f; }
    __syncthreads();

    float rs[4][2] = {{0.f,0.f},{0.f,0.f},{0.f,0.f},{0.f,0.f}};
    float cs[4][2] = {{0.f,0.f},{0.f,0.f},{0.f,0.f},{0.f,0.f}};
#pragma unroll
    for (int mf = 0; mf < 4; mf++) {
        int row = i0 + wm * 64 + mf * 16 + g;
#pragma unroll
        for (int nf = 0; nf < 4; nf++) {
            int col = j0 + wn * 32 + nf * 8 + 2 * t;
            float p0 = __expf(acc[mf][nf][0] * SCALE_);
            float p1 = __expf(acc[mf][nf][1] * SCALE_);
            float p2 = __expf(acc[mf][nf][2] * SCALE_);
            float p3 = __expf(acc[mf][nf][3] * SCALE_);
            *(float2*)&Pp[(size_t)row * N_ + col]       = make_float2(p0, p1);
            *(float2*)&Pp[(size_t)(row + 8) * N_ + col] = make_float2(p2, p3);
            rs[mf][0] += p0 + p1; rs[mf][1] += p2 + p3;
            cs[nf][0] += p0 + p2; cs[nf][1] += p1 + p3;
        }
    }
#pragma unroll
    for (int mf = 0; mf < 4; mf++)
#pragma unroll
        for (int h = 0; h < 2; h++) {
            float v = rs[mf][h];
            v += __shfl_xor_sync(0xffffffffu, v, 1);
            v += __shfl_xor_sync(0xffffffffu, v, 2);
            if (t == 0) atomicAdd(&shr[wm * 64 + mf * 16 + h * 8 + g], v);
        }
#pragma unroll
    for (int nf = 0; nf < 4; nf++)
#pragma unroll
        for (int q = 0; q < 2; q++) {
            float v = cs[nf][q];
            v += __shfl_xor_sync(0xffffffffu, v, 4);
            v += __shfl_xor_sync(0xffffffffu, v, 8);
            v += __shfl_xor_sync(0xffffffffu, v, 16);
            if (g == 0) atomicAdd(&shc[wn * 32 + nf * 8 + 2 * t + q], v);
        }
    __syncthreads();
    if (tid < 128) {
        atomicAdd(&g_rsum[b * N_ + i0 + tid], shr[tid]);
        atomicAdd(&g_csum[b * N_ + j0 + tid], shc[tid]);
    }
}

// ---------------- kernel 4: AV GEMMs (tf32 single-pass, cvt at fill) ---------
__global__ __launch_bounds__(256, 2) void k_av() {
    const int mode = blockIdx.x;
    const int b    = blockIdx.z;
    const int i0   = blockIdx.y * 128;
    const float* Pp  = g_S + (size_t)b * N_ * N_;
    const float* V   = (mode == 0 ? g_rp : g_ri) + (size_t)b * N_ * PC_;
    const float* sum = (mode == 0 ? g_csum : g_rsum) + b * N_;
    float*       D   = (mode == 0 ? g_outp : g_outi) + (size_t)b * N_ * PC_;

    __shared__ unsigned As[16][LDM];
    __shared__ unsigned Bs[16][LDM];

    const int tid  = threadIdx.x;
    const int lane = tid & 31, wid = tid >> 5;
    const int wm = wid & 1, wn = wid >> 1;
    const int g = lane >> 2, t = lane & 3;

    float acc[4][4][4];
#pragma unroll
    for (int mf = 0; mf < 4; mf++)
#pragma unroll
        for (int nf = 0; nf < 4; nf++)
#pragma unroll
            for (int q = 0; q < 4; q++) acc[mf][nf][q] = 0.f;

    for (int k0 = 0; k0 < N_; k0 += 16) {
        if (mode == 0) {      // As[k][i] = P[(i0+i)*N + k0+k]
#pragma unroll
            for (int r = 0; r < 2; r++) {
                int idx = tid + r * 256;
                int i = idx >> 2, c = (idx & 3) * 4;
                float4 v = *(const float4*)&Pp[(size_t)(i0 + i) * N_ + k0 + c];
                As[c + 0][i] = tf32_of(v.x); As[c + 1][i] = tf32_of(v.y);
                As[c + 2][i] = tf32_of(v.z); As[c + 3][i] = tf32_of(v.w);
            }
        } else {              // As[k][i] = P[(k0+k)*N + i0+i]
#pragma unroll
            for (int r = 0; r < 2; r++) {
                int idx = tid + r * 256;
                int k = idx >> 5, ic = (idx & 31) * 4;
                float4 v = *(const float4*)&Pp[(size_t)(k0 + k) * N_ + i0 + ic];
                As[k][ic + 0] = tf32_of(v.x); As[k][ic + 1] = tf32_of(v.y);
                As[k][ic + 2] = tf32_of(v.z); As[k][ic + 3] = tf32_of(v.w);
            }
        }
        {                     // Bs[k][d] = V[(k0+k)*128 + d] / sum[k0+k]
#pragma unroll
            for (int r = 0; r < 2; r++) {
                int idx = tid + r * 256;
                int k = idx >> 5, dc = (idx & 31) * 4;
                float inv = __fdividef(1.0f, sum[k0 + k]);
                float4 v = *(const float4*)&V[(size_t)(k0 + k) * PC_ + dc];
                Bs[k][dc + 0] = tf32_of(v.x * inv); Bs[k][dc + 1] = tf32_of(v.y * inv);
                Bs[k][dc + 2] = tf32_of(v.z * inv); Bs[k][dc + 3] = tf32_of(v.w * inv);
            }
        }
        __syncthreads();
#pragma unroll
        for (int kk = 0; kk < 16; kk += 8) {
            unsigned a[4][4], bb[4][2];
#pragma unroll
            for (int mf = 0; mf < 4; mf++) {
                int m = wm * 64 + mf * 16 + g;
                a[mf][0] = As[kk + t][m];
                a[mf][1] = As[kk + t][m + 8];
                a[mf][2] = As[kk + t + 4][m];
                a[mf][3] = As[kk + t + 4][m + 8];
            }
#pragma unroll
            for (int nf = 0; nf < 4; nf++) {
                int n = wn * 32 + nf * 8 + g;
                bb[nf][0] = Bs[kk + t][n];
                bb[nf][1] = Bs[kk + t + 4][n];
            }
#pragma unroll
            for (int mf = 0; mf < 4; mf++)
#pragma unroll
                for (int nf = 0; nf < 4; nf++)
                    mma_tf32(acc[mf][nf], a[mf][0], a[mf][1], a[mf][2], a[mf][3],
                             bb[nf][0], bb[nf][1]);
        }
        __syncthreads();
    }
#pragma unroll
    for (int mf = 0; mf < 4; mf++) {
        int row = i0 + wm * 64 + mf * 16 + g;
#pragma unroll
        for (int nf = 0; nf < 4; nf++) {
            int col = wn * 32 + nf * 8 + 2 * t;
            *(float2*)&D[(size_t)row * PC_ + col]       = make_float2(acc[mf][nf][0], acc[mf][nf][1]);
            *(float2*)&D[(size_t)(row + 8) * PC_ + col] = make_float2(acc[mf][nf][2], acc[mf][nf][3]);
        }
    }
}

// ---------------- kernel 5: conv1d(k=1) + BN(eval) + ReLU  (scalar fp32) -----
__global__ void k_conv(const float* __restrict__ w,     const float* __restrict__ cb,
                       const float* __restrict__ gamma, const float* __restrict__ beta,
                       const float* __restrict__ mean,  const float* __restrict__ var,
                       float* __restrict__ out) {
    const int b  = blockIdx.z;
    const int n0 = blockIdx.x * 64;
    const float* P = g_outp + (size_t)b * N_ * PC_;
    const float* I = g_outi + (size_t)b * N_ * PC_;
    __shared__ float As[16][128];
    __shared__ float Bs[16][64];
    const int tx = threadIdx.x, ty = threadIdx.y;
    const int tid = ty * 16 + tx;
    float acc[8][4];
#pragma unroll
    for (int i = 0; i < 8; i++)
#pragma unroll
        for (int j = 0; j < 4; j++) acc[i][j] = 0.f;

    for (int k0 = 0; k0 < 2 * PC_; k0 += 16) {
        {
            int l = tid * 8, oo = l / 16, kk = l % 16;
            float4 v0 = *(const float4*)&w[(size_t)oo * (2 * PC_) + k0 + kk];
            float4 v1 = *(const float4*)&w[(size_t)oo * (2 * PC_) + k0 + kk + 4];
            As[kk + 0][oo] = v0.x; As[kk + 1][oo] = v0.y;
            As[kk + 2][oo] = v0.z; As[kk + 3][oo] = v0.w;
            As[kk + 4][oo] = v1.x; As[kk + 5][oo] = v1.y;
            As[kk + 6][oo] = v1.z; As[kk + 7][oo] = v1.w;
        }
        {
            int l = tid * 4, nn = l / 16, kk = l % 16;
            const float* src = (k0 < PC_) ? &P[(size_t)(n0 + nn) * PC_ + k0 + kk]
                                          : &I[(size_t)(n0 + nn) * PC_ + k0 - PC_ + kk];
            float4 v = *(const float4*)src;
            Bs[kk + 0][nn] = v.x; Bs[kk + 1][nn] = v.y;
            Bs[kk + 2][nn] = v.z; Bs[kk + 3][nn] = v.w;
        }
        __syncthreads();
#pragma unroll
        for (int kk = 0; kk < 16; kk++) {
            float a[8], bb[4];
#pragma unroll
            for (int i = 0; i < 8; i++) a[i] = As[kk][ty * 8 + i];
#pragma unroll
            for (int j = 0; j < 4; j++) bb[j] = Bs[kk][tx * 4 + j];
#pragma unroll
            for (int i = 0; i < 8; i++)
#pragma unroll
                for (int j = 0; j < 4; j++) acc[i][j] += a[i] * bb[j];
        }
        __syncthreads();
    }
#pragma unroll
    for (int i = 0; i < 8; i++) {
        int o = ty * 8 + i;
        float gm   = gamma[o] * rsqrtf(var[o] + 1e-5f);
        float base = gm * (cb[o] - mean[o]) + beta[o];
        float4 v;
        v.x = fmaxf(gm * acc[i][0] + base, 0.f);
        v.y = fmaxf(gm * acc[i][1] + base, 0.f);
        v.z = fmaxf(gm * acc[i][2] + base, 0.f);
        v.w = fmaxf(gm * acc[i][3] + base, 0.f);
        *(float4*)&out[(size_t)b * OC_ * N_ + (size_t)o * N_ + n0 + tx * 4] = v;
    }
}

// ---------------- launch -----------------------------------------------------
extern "C" void kernel_launch(void* const* d_in, const int* in_sizes, int n_in,
                              void* d_out, int out_size) {
    const float* pf     = (const float*)d_in[0];
    const float* img    = (const float*)d_in[1];
    const float* fc2_w  = (const float*)d_in[2];
    const float* fc2_b  = (const float*)d_in[3];
    const float* conv_w = (const float*)d_in[4];
    const float* conv_b = (const float*)d_in[5];
    const float* gamma  = (const float*)d_in[6];
    const float* beta   = (const float*)d_in[7];
    const float* mean   = (const float*)d_in[8];
    const float* var    = (const float*)d_in[9];
    float* out = (float*)d_out;

    k_zero     <<<(B_ * N_ + 511) / 512, 512>>>();
    k_transpose<<<dim3(N_ / 32, PC_ / 32, B_), dim3(32, 8)>>>(pf);
    k_ri       <<<dim3(1, N_ / 64, B_),        dim3(16, 16)>>>(img, fc2_w, fc2_b);
    k_s        <<<dim3(N_ / 128, N_ / 128, B_), 256>>>();
    k_av       <<<dim3(2, N_ / 128, B_),        256>>>();
    k_conv     <<<dim3(N_ / 64, 1, B_),        dim3(16, 16)>>>(conv_w, conv_b, gamma, beta,
                                                               mean, var, out);
}